// round 3
// baseline (speedup 1.0000x reference)
#include <cuda_runtime.h>
#include <cstdint>

#define B_ 64
#define T_ 96
#define NV 4
#define NK_ 12
#define NF_ 17
#define HW_ 400
#define SIGLEN_ 306
#define KTOT_ 122400        // HW_*SIGLEN_
#define NCHUNK_ 255
#define KC_ 480             // NCHUNK_*KC_ == KTOT_
#define PT_ 40              // pixels per sig block

// Scratch (static __device__ arrays; no allocation allowed in kernel_launch)
__device__ float g_feat[(size_t)B_ * T_ * NF_ * HW_];   // [b][t][f][p]  ~167 MB
__device__ float g_sig [(size_t)B_ * HW_ * SIGLEN_];    // [b][p][s]     ~31 MB
__device__ float g_part[(size_t)NCHUNK_ * 64 * 32];

// ---------------------------------------------------------------------------
// Kernel 1: conv3x3 (4->12, SAME) + copy x + time channel  -> g_feat
// One block per (b,t) image. 160 threads = 4 k-groups x 40 threads.
// Thread: 3 output channels (weights in regs) x 10 pixels, contiguous
// lane->pixel mapping for coalesced stores.
// ---------------------------------------------------------------------------
__global__ __launch_bounds__(160, 2)
void conv_kernel(const float* __restrict__ x,
                 const float* __restrict__ cw,
                 const float* __restrict__ cb)
{
    __shared__ float xs[4 * 484];   // 4 vars, padded 22x22
    __shared__ float ws[444];       // 432 weights + 12 bias

    const int bid = blockIdx.x;     // b*96 + t
    const int t   = bid % T_;
    const int tid = threadIdx.x;
    const float* xg = x + (size_t)bid * NV * HW_;

    for (int i = tid; i < 4 * 484; i += 160) {
        int v = i / 484, r = i % 484, yy = r / 22, xx = r % 22;
        float val = 0.f;
        if (yy >= 1 && yy <= 20 && xx >= 1 && xx <= 20)
            val = xg[v * HW_ + (yy - 1) * 20 + (xx - 1)];
        xs[i] = val;
    }
    for (int i = tid; i < 444; i += 160)
        ws[i] = (i < 432) ? cw[i] : cb[i - 432];
    __syncthreads();

    const int kg = tid / 40, lane = tid % 40;
    const int k0 = kg * 3;
    const int y0 = lane / 20, xc = lane % 20;

    float wr[3][36];
#pragma unroll
    for (int kk = 0; kk < 3; kk++)
#pragma unroll
        for (int tap = 0; tap < 36; tap++)
            wr[kk][tap] = ws[(k0 + kk) * 36 + tap];
    const float bi0 = ws[432 + k0], bi1 = ws[432 + k0 + 1], bi2 = ws[432 + k0 + 2];

    float* fo = g_feat + (size_t)bid * NF_ * HW_;

#pragma unroll
    for (int p = 0; p < 10; p++) {
        const float* base = xs + (y0 + 2 * p) * 22 + xc;
        float a0 = bi0, a1 = bi1, a2 = bi2;
#pragma unroll
        for (int v = 0; v < 4; v++)
#pragma unroll
            for (int dy = 0; dy < 3; dy++)
#pragma unroll
                for (int dx = 0; dx < 3; dx++) {
                    const float xv = base[v * 484 + dy * 22 + dx];
                    const int tap = v * 9 + dy * 3 + dx;
                    a0 = fmaf(wr[0][tap], xv, a0);
                    a1 = fmaf(wr[1][tap], xv, a1);
                    a2 = fmaf(wr[2][tap], xv, a2);
                }
        const int pg = lane + 40 * p;
        fo[(k0 + 0) * HW_ + pg] = a0;
        fo[(k0 + 1) * HW_ + pg] = a1;
        fo[(k0 + 2) * HW_ + pg] = a2;
    }

    // features 12..15 = x vars, 16 = time channel (coalesced)
    const float tval = (float)t * (1.0f / 95.0f);
    for (int i = tid; i < 5 * HW_; i += 160) {
        const int f = 12 + i / HW_, pg = i % HW_;
        float val;
        if (f < 16) {
            const int v = f - 12;
            val = xs[v * 484 + (pg / 20 + 1) * 22 + (pg % 20 + 1)];
        } else val = tval;
        fo[f * HW_ + pg] = val;
    }
}

// ---------------------------------------------------------------------------
// Kernel 2: path signature, spill-free config.
// lvl1_j = p_{95,j} - p_{0,j}
// lvl2_ij = 0.5 * sum_t (p_t + p_{t-1})_i (p_t - p_{t-1})_j  -  p0_i * lvl1_j
// Block = 160 threads: 40 pixels x 4 quadrant-threads (9x9 each).
// occupancy 2 -> 204-reg cap (need ~125) -> no spill. Base+stride load
// indexing (160 = 4*40 so f steps by exactly 4 per load leg).
// ---------------------------------------------------------------------------
__global__ __launch_bounds__(160, 2)
void sig_kernel()
{
    __shared__ float cur[2][17 * 41];

    const int b = blockIdx.y, cx = blockIdx.x;
    const int pbase = cx * PT_;
    const int tid = threadIdx.x;
    const int pp = tid >> 2, q = tid & 3;
    const int i0 = (q >> 1) * 8, j0 = (q & 1) * 8;

    const float* fb = g_feat + (size_t)b * T_ * NF_ * HW_ + pbase;

    const int p_ = tid % PT_, f0 = tid / PT_;   // load leg l: f = f0 + 4l
    const int g0 = f0 * HW_ + p_;               // gmem offset, stride 4*HW_
    const int s0 = f0 * 41 + p_;                // smem offset, stride 4*41

    // t = 0
#pragma unroll
    for (int l = 0; l < 5; l++)
        if (f0 + 4 * l < NF_) cur[0][s0 + l * (4 * 41)] = fb[g0 + l * (4 * HW_)];
    __syncthreads();

    float pi[9], pj[9], acc[9][9];
#pragma unroll
    for (int a = 0; a < 9; a++) pi[a] = cur[0][(i0 + a) * 41 + pp];
#pragma unroll
    for (int c = 0; c < 9; c++) pj[c] = cur[0][(j0 + c) * 41 + pp];
#pragma unroll
    for (int a = 0; a < 9; a++)
#pragma unroll
        for (int c = 0; c < 9; c++) acc[a][c] = 0.f;

    // prefetch t=1
    float rv[5];
    {
        const float* fn = fb + (size_t)NF_ * HW_;
#pragma unroll
        for (int l = 0; l < 5; l++)
            if (f0 + 4 * l < NF_) rv[l] = fn[g0 + l * (4 * HW_)];
    }

    for (int t = 1; t < T_; t++) {
        const int buf = t & 1;
#pragma unroll
        for (int l = 0; l < 5; l++)
            if (f0 + 4 * l < NF_) cur[buf][s0 + l * (4 * 41)] = rv[l];
        if (t < T_ - 1) {
            const float* fn = fb + (size_t)(t + 1) * NF_ * HW_;
#pragma unroll
            for (int l = 0; l < 5; l++)
                if (f0 + 4 * l < NF_) rv[l] = fn[g0 + l * (4 * HW_)];
        }
        __syncthreads();

        float d[9];
#pragma unroll
        for (int c = 0; c < 9; c++) {
            const float cv = cur[buf][(j0 + c) * 41 + pp];
            d[c] = cv - pj[c];
            pj[c] = cv;
        }
#pragma unroll
        for (int a = 0; a < 9; a++) {
            const float cv = cur[buf][(i0 + a) * 41 + pp];
            const float m = cv + pi[a];      // (p_t + p_{t-1})_i, 0.5 deferred
            pi[a] = cv;
#pragma unroll
            for (int c = 0; c < 9; c++)
                acc[a][c] = fmaf(m, d[c], acc[a][c]);
        }
    }

    // epilogue: re-read p0 from gmem, assemble signature
    float p0i[9], l1[9];
#pragma unroll
    for (int a = 0; a < 9; a++) p0i[a] = fb[(i0 + a) * HW_ + pp];
#pragma unroll
    for (int c = 0; c < 9; c++) {
        const float p0j = fb[(j0 + c) * HW_ + pp];
        l1[c] = pj[c] - p0j;
    }

    float* sg = g_sig + ((size_t)b * HW_ + pbase + pp) * SIGLEN_;
    if (q < 2) {
#pragma unroll
        for (int c = 0; c < 9; c++) sg[j0 + c] = l1[c];
    }
#pragma unroll
    for (int a = 0; a < 9; a++)
#pragma unroll
        for (int c = 0; c < 9; c++)
            sg[17 + (i0 + a) * 17 + (j0 + c)] = 0.5f * acc[a][c] - p0i[a] * l1[c];
}

// ---------------------------------------------------------------------------
// Kernel 3: layer-1 GEMM partials over K=122400 split into 255 chunks of 480.
// Register prefetch of next 32-K tile. Thread owns 2b x 4o.
// ---------------------------------------------------------------------------
__global__ __launch_bounds__(256)
void mlp1_kernel(const float* __restrict__ w1)
{
    __shared__ __align__(16) float ss[32 * 66];
    __shared__ __align__(16) float wsm[32 * 32];

    const int cx = blockIdx.x, tid = threadIdx.x;
    const int oq = tid & 7, bq = tid >> 3;
    const int b0 = bq * 2, o0 = oq * 4;
    const int kb = cx * KC_;

    float ps[8], pw[4];
    {
        const int k0 = kb;
#pragma unroll
        for (int r = 0; r < 8; r++) {
            const int idx = tid + r * 256;
            ps[r] = g_sig[(size_t)(idx >> 5) * KTOT_ + k0 + (idx & 31)];
        }
#pragma unroll
        for (int r = 0; r < 4; r++) {
            const int idx = tid + r * 256;
            pw[r] = w1[(size_t)(k0 + (idx >> 5)) * 32 + (idx & 31)];
        }
    }

    float acc[2][4] = {};

    for (int tile = 0; tile < KC_ / 32; tile++) {
#pragma unroll
        for (int r = 0; r < 8; r++) {
            const int idx = tid + r * 256;
            ss[(idx & 31) * 66 + (idx >> 5)] = ps[r];
        }
#pragma unroll
        for (int r = 0; r < 4; r++) {
            const int idx = tid + r * 256;
            wsm[(idx >> 5) * 32 + (idx & 31)] = pw[r];
        }
        if (tile < KC_ / 32 - 1) {
            const int k0 = kb + (tile + 1) * 32;
#pragma unroll
            for (int r = 0; r < 8; r++) {
                const int idx = tid + r * 256;
                ps[r] = g_sig[(size_t)(idx >> 5) * KTOT_ + k0 + (idx & 31)];
            }
#pragma unroll
            for (int r = 0; r < 4; r++) {
                const int idx = tid + r * 256;
                pw[r] = w1[(size_t)(k0 + (idx >> 5)) * 32 + (idx & 31)];
            }
        }
        __syncthreads();
#pragma unroll
        for (int kk = 0; kk < 32; kk++) {
            const float2 sv = *(const float2*)&ss[kk * 66 + b0];
            const float4 wv = *(const float4*)&wsm[kk * 32 + o0];
            acc[0][0] = fmaf(sv.x, wv.x, acc[0][0]);
            acc[0][1] = fmaf(sv.x, wv.y, acc[0][1]);
            acc[0][2] = fmaf(sv.x, wv.z, acc[0][2]);
            acc[0][3] = fmaf(sv.x, wv.w, acc[0][3]);
            acc[1][0] = fmaf(sv.y, wv.x, acc[1][0]);
            acc[1][1] = fmaf(sv.y, wv.y, acc[1][1]);
            acc[1][2] = fmaf(sv.y, wv.z, acc[1][2]);
            acc[1][3] = fmaf(sv.y, wv.w, acc[1][3]);
        }
        __syncthreads();
    }
#pragma unroll
    for (int i = 0; i < 2; i++)
#pragma unroll
        for (int j = 0; j < 4; j++)
            g_part[((size_t)cx * 64 + b0 + i) * 32 + o0 + j] = acc[i][j];
}

// ---------------------------------------------------------------------------
// Kernel 4: reduce partials (256 threads) + bias/relu + layers 2..4 in warp 0.
// ---------------------------------------------------------------------------
__global__ __launch_bounds__(256)
void mlp_tail_kernel(const float* __restrict__ b1,
                     const float* __restrict__ w2, const float* __restrict__ b2,
                     const float* __restrict__ w3, const float* __restrict__ b3,
                     const float* __restrict__ w4, const float* __restrict__ b4,
                     float* __restrict__ out)
{
    __shared__ float red[8][33];
    const int b = blockIdx.x, tid = threadIdx.x;
    const int o = tid & 31, g = tid >> 5;

    float s = 0.f;
    for (int c = g; c < NCHUNK_; c += 8)
        s += g_part[((size_t)c * 64 + b) * 32 + o];
    red[g][o] = s;
    __syncthreads();

    if (tid < 32) {
        float s1 = b1[o];
#pragma unroll
        for (int gg = 0; gg < 8; gg++) s1 += red[gg][o];
        float h = fmaxf(s1, 0.f);

        float s2 = b2[o];
#pragma unroll
        for (int k = 0; k < 32; k++)
            s2 = fmaf(__shfl_sync(0xffffffffu, h, k), w2[k * 32 + o], s2);
        h = fmaxf(s2, 0.f);

        float s3 = b3[o];
#pragma unroll
        for (int k = 0; k < 32; k++)
            s3 = fmaf(__shfl_sync(0xffffffffu, h, k), w3[k * 32 + o], s3);
        h = fmaxf(s3, 0.f);

        float v = h * w4[o];
#pragma unroll
        for (int off = 16; off; off >>= 1) v += __shfl_xor_sync(0xffffffffu, v, off);
        if (o == 0) out[b] = v + b4[0];
    }
}

// ---------------------------------------------------------------------------
extern "C" void kernel_launch(void* const* d_in, const int* in_sizes, int n_in,
                              void* d_out, int out_size)
{
    const float* x  = (const float*)d_in[0];
    const float* cw = (const float*)d_in[1];
    const float* cb = (const float*)d_in[2];
    const float* w1 = (const float*)d_in[3];
    const float* b1 = (const float*)d_in[4];
    const float* w2 = (const float*)d_in[5];
    const float* b2 = (const float*)d_in[6];
    const float* w3 = (const float*)d_in[7];
    const float* b3 = (const float*)d_in[8];
    const float* w4 = (const float*)d_in[9];
    const float* b4 = (const float*)d_in[10];
    float* out = (float*)d_out;

    conv_kernel<<<B_ * T_, 160>>>(x, cw, cb);
    sig_kernel<<<dim3(HW_ / PT_, B_), 160>>>();
    mlp1_kernel<<<NCHUNK_, 256>>>(w1);
    mlp_tail_kernel<<<B_, 256>>>(b1, w2, b2, w3, b3, w4, b4, out);
}

// round 4
// speedup vs baseline: 1.2192x; 1.2192x over previous
#include <cuda_runtime.h>
#include <cstdint>

#define B_ 64
#define T_ 96
#define NV 4
#define NK_ 12
#define NF_ 17
#define HW_ 400
#define SIGLEN_ 306
#define KTOT_ 122400        // HW_*SIGLEN_
#define NCHUNK_ 255
#define KC_ 480             // NCHUNK_*KC_ == KTOT_

__device__ float g_sig [(size_t)B_ * HW_ * SIGLEN_];    // [b][p][s]  ~31 MB
__device__ float g_part[(size_t)NCHUNK_ * 64 * 32];

// ---------------------------------------------------------------------------
// Fused kernel: conv3x3(4->12) + feature assembly + path signature.
// Grid (4, 64): block = (5-row pixel strip of 100 px, batch b). 400 threads.
// Per t: stage x_t slice (7x22x4 halo, zero-padded) -> conv into smem feat
// tile (double-buffered) -> signature update. No global feat buffer at all.
//
// sig math (validated r1-r3):
//   lvl1_j  = p95_j - p0_j
//   lvl2_ij = 0.5 * sum_t (p_t+p_{t-1})_i (p_t-p_{t-1})_j - p0_i*lvl1_j
// ---------------------------------------------------------------------------
__global__ __launch_bounds__(400, 1)
void fused_conv_sig_kernel(const float* __restrict__ x,
                           const float* __restrict__ cw,
                           const float* __restrict__ cb)
{
    __shared__ __align__(16) float xs[616];            // 4 vars x 7 x 22, zero-padded halo
    __shared__ __align__(16) float ws2[12 * 48];       // weights [k][v][12pad]
    __shared__ float wb[12];                           // bias
    __shared__ __align__(16) float feat[2][17 * 101];  // double-buffered feature tile
    __shared__ float p0s[17 * 101];                    // t=0 snapshot

    const int cx = blockIdx.x;          // pixel strip: rows 5cx..5cx+4
    const int b  = blockIdx.y;
    const int tid = threadIdx.x;
    const int pbase = cx * 100;

    // ---- one-time init ----
    // zero xs (halo guard slots stay 0 forever)
    for (int i = tid; i < 616; i += 400) xs[i] = 0.f;
    // repack weights: cw[k*36 + v*9 + tap] -> ws2[k*48 + v*12 + tap]
    for (int i = tid; i < 432; i += 400) {
        const int k = i / 36, r = i % 36, v = r / 9, tap = r % 9;
        ws2[k * 48 + v * 12 + tap] = cw[i];
    }
    if (tid < 12) wb[tid] = cb[tid];

    // hoisted x-staging indices (2 legs)
    const float* xg = x + (size_t)b * T_ * NV * HW_;
    int gofA = -1, sofA = 0, gofB = -1, sofB = 0;
    {
        const int i = tid;  // always < 616
        const int v = i / 154, r = i % 154, row = r / 22, col = r % 22;
        const int gr = cx * 5 - 1 + row;
        if (gr >= 0 && gr < 20 && col >= 1 && col <= 20) {
            gofA = v * HW_ + gr * 20 + (col - 1);
            sofA = i;
        }
    }
    if (tid + 400 < 616) {
        const int i = tid + 400;
        const int v = i / 154, r = i % 154, row = r / 22, col = r % 22;
        const int gr = cx * 5 - 1 + row;
        if (gr >= 0 && gr < 20 && col >= 1 && col <= 20) {
            gofB = v * HW_ + gr * 20 + (col - 1);
            sofB = i;
        }
    }

    // conv-role mapping: px = tid%100 (channel group kq = tid/100 owns ch 3kq..3kq+2)
    const int px = tid % 100, kq = tid / 100;
    const int row0 = px / 20, col0 = px % 20;
    const float* xrow = xs + row0 * 22 + col0;

    // sig-role mapping: pixel pp, quadrant q
    const int pp = tid >> 2, q = tid & 3;
    const int i0 = (q >> 1) * 8, j0 = (q & 1) * 8;

    __syncthreads();   // ws2/wb ready

    const float bi0 = wb[kq * 3], bi1 = wb[kq * 3 + 1], bi2 = wb[kq * 3 + 2];

    // prefetch x_0
    float rvA = 0.f, rvB = 0.f;
    if (gofA >= 0) rvA = xg[gofA];
    if (gofB >= 0) rvB = xg[gofB];

    float pi[9], pj[9], acc[9][9];
#pragma unroll
    for (int a = 0; a < 9; a++)
#pragma unroll
        for (int c = 0; c < 9; c++) acc[a][c] = 0.f;

    for (int t = 0; t < T_; t++) {
        const int buf = t & 1;
        float* ft = feat[buf];

        // phase A: stage x_t, prefetch x_{t+1}
        if (gofA >= 0) xs[sofA] = rvA;
        if (gofB >= 0) xs[sofB] = rvB;
        if (t < T_ - 1) {
            const float* xn = xg + (size_t)(t + 1) * NV * HW_;
            if (gofA >= 0) rvA = xn[gofA];
            if (gofB >= 0) rvB = xn[gofB];
        }
        __syncthreads();   // xs ready; everyone past sig(t-1)

        // phase B: conv for this thread's pixel, 3 channels
        {
            float a0 = bi0, a1 = bi1, a2 = bi2;
#pragma unroll
            for (int v = 0; v < 4; v++) {
                float xv[9];
#pragma unroll
                for (int dy = 0; dy < 3; dy++)
#pragma unroll
                    for (int dx = 0; dx < 3; dx++)
                        xv[dy * 3 + dx] = xrow[v * 154 + dy * 22 + dx];
#pragma unroll
                for (int c = 0; c < 3; c++) {
                    const float4* wp = (const float4*)(ws2 + (kq * 3 + c) * 48 + v * 12);
                    const float4 w0 = wp[0];
                    const float4 w1 = wp[1];
                    const float w8 = ws2[(kq * 3 + c) * 48 + v * 12 + 8];
                    float s = xv[0] * w0.x;
                    s = fmaf(xv[1], w0.y, s);
                    s = fmaf(xv[2], w0.z, s);
                    s = fmaf(xv[3], w0.w, s);
                    s = fmaf(xv[4], w1.x, s);
                    s = fmaf(xv[5], w1.y, s);
                    s = fmaf(xv[6], w1.z, s);
                    s = fmaf(xv[7], w1.w, s);
                    s = fmaf(xv[8], w8, s);
                    if (c == 0) a0 += s; else if (c == 1) a1 += s; else a2 += s;
                }
            }
            ft[(kq * 3 + 0) * 101 + px] = a0;
            ft[(kq * 3 + 1) * 101 + px] = a1;
            ft[(kq * 3 + 2) * 101 + px] = a2;
            // copy-x channel 12+kq, and time channel (kq==0)
            ft[(12 + kq) * 101 + px] = xrow[kq * 154 + 22 + 1];  // xs[kq][row0+1][col0+1]
            if (kq == 0) ft[16 * 101 + px] = (float)t * (1.0f / 95.0f);
        }
        __syncthreads();   // feat[buf] ready

        // phase C: signature update
        if (t == 0) {
#pragma unroll
            for (int a = 0; a < 9; a++) pi[a] = ft[(i0 + a) * 101 + pp];
#pragma unroll
            for (int c = 0; c < 9; c++) pj[c] = ft[(j0 + c) * 101 + pp];
            for (int i = tid; i < 17 * 101; i += 400) p0s[i] = ft[i];
        } else {
            float d[9];
#pragma unroll
            for (int c = 0; c < 9; c++) {
                const float cv = ft[(j0 + c) * 101 + pp];
                d[c] = cv - pj[c];
                pj[c] = cv;
            }
#pragma unroll
            for (int a = 0; a < 9; a++) {
                const float cv = ft[(i0 + a) * 101 + pp];
                const float m = cv + pi[a];      // 0.5 deferred
                pi[a] = cv;
#pragma unroll
                for (int c = 0; c < 9; c++)
                    acc[a][c] = fmaf(m, d[c], acc[a][c]);
            }
        }
    }

    // epilogue
    float p0i[9], l1[9];
#pragma unroll
    for (int a = 0; a < 9; a++) p0i[a] = p0s[(i0 + a) * 101 + pp];
#pragma unroll
    for (int c = 0; c < 9; c++) l1[c] = pj[c] - p0s[(j0 + c) * 101 + pp];

    float* sg = g_sig + ((size_t)b * HW_ + pbase + pp) * SIGLEN_;
    if (q < 2) {
#pragma unroll
        for (int c = 0; c < 9; c++) sg[j0 + c] = l1[c];
    }
#pragma unroll
    for (int a = 0; a < 9; a++)
#pragma unroll
        for (int c = 0; c < 9; c++)
            sg[17 + (i0 + a) * 17 + (j0 + c)] = 0.5f * acc[a][c] - p0i[a] * l1[c];
}

// ---------------------------------------------------------------------------
// Kernel 3: layer-1 GEMM partials over K=122400, 255 chunks of 480.
// Register prefetch of next 32-K tile. Thread owns 2b x 4o.
// ---------------------------------------------------------------------------
__global__ __launch_bounds__(256)
void mlp1_kernel(const float* __restrict__ w1)
{
    __shared__ __align__(16) float ss[32 * 66];
    __shared__ __align__(16) float wsm[32 * 32];

    const int cx = blockIdx.x, tid = threadIdx.x;
    const int oq = tid & 7, bq = tid >> 3;
    const int b0 = bq * 2, o0 = oq * 4;
    const int kb = cx * KC_;

    float ps[8], pw[4];
    {
        const int k0 = kb;
#pragma unroll
        for (int r = 0; r < 8; r++) {
            const int idx = tid + r * 256;
            ps[r] = g_sig[(size_t)(idx >> 5) * KTOT_ + k0 + (idx & 31)];
        }
#pragma unroll
        for (int r = 0; r < 4; r++) {
            const int idx = tid + r * 256;
            pw[r] = w1[(size_t)(k0 + (idx >> 5)) * 32 + (idx & 31)];
        }
    }

    float acc[2][4] = {};

    for (int tile = 0; tile < KC_ / 32; tile++) {
#pragma unroll
        for (int r = 0; r < 8; r++) {
            const int idx = tid + r * 256;
            ss[(idx & 31) * 66 + (idx >> 5)] = ps[r];
        }
#pragma unroll
        for (int r = 0; r < 4; r++) {
            const int idx = tid + r * 256;
            wsm[(idx >> 5) * 32 + (idx & 31)] = pw[r];
        }
        if (tile < KC_ / 32 - 1) {
            const int k0 = kb + (tile + 1) * 32;
#pragma unroll
            for (int r = 0; r < 8; r++) {
                const int idx = tid + r * 256;
                ps[r] = g_sig[(size_t)(idx >> 5) * KTOT_ + k0 + (idx & 31)];
            }
#pragma unroll
            for (int r = 0; r < 4; r++) {
                const int idx = tid + r * 256;
                pw[r] = w1[(size_t)(k0 + (idx >> 5)) * 32 + (idx & 31)];
            }
        }
        __syncthreads();
#pragma unroll
        for (int kk = 0; kk < 32; kk++) {
            const float2 sv = *(const float2*)&ss[kk * 66 + b0];
            const float4 wv = *(const float4*)&wsm[kk * 32 + o0];
            acc[0][0] = fmaf(sv.x, wv.x, acc[0][0]);
            acc[0][1] = fmaf(sv.x, wv.y, acc[0][1]);
            acc[0][2] = fmaf(sv.x, wv.z, acc[0][2]);
            acc[0][3] = fmaf(sv.x, wv.w, acc[0][3]);
            acc[1][0] = fmaf(sv.y, wv.x, acc[1][0]);
            acc[1][1] = fmaf(sv.y, wv.y, acc[1][1]);
            acc[1][2] = fmaf(sv.y, wv.z, acc[1][2]);
            acc[1][3] = fmaf(sv.y, wv.w, acc[1][3]);
        }
        __syncthreads();
    }
#pragma unroll
    for (int i = 0; i < 2; i++)
#pragma unroll
        for (int j = 0; j < 4; j++)
            g_part[((size_t)cx * 64 + b0 + i) * 32 + o0 + j] = acc[i][j];
}

// ---------------------------------------------------------------------------
// Kernel 4: reduce partials (256 threads) + bias/relu + layers 2..4 in warp 0.
// ---------------------------------------------------------------------------
__global__ __launch_bounds__(256)
void mlp_tail_kernel(const float* __restrict__ b1,
                     const float* __restrict__ w2, const float* __restrict__ b2,
                     const float* __restrict__ w3, const float* __restrict__ b3,
                     const float* __restrict__ w4, const float* __restrict__ b4,
                     float* __restrict__ out)
{
    __shared__ float red[8][33];
    const int b = blockIdx.x, tid = threadIdx.x;
    const int o = tid & 31, g = tid >> 5;

    float s = 0.f;
    for (int c = g; c < NCHUNK_; c += 8)
        s += g_part[((size_t)c * 64 + b) * 32 + o];
    red[g][o] = s;
    __syncthreads();

    if (tid < 32) {
        float s1 = b1[o];
#pragma unroll
        for (int gg = 0; gg < 8; gg++) s1 += red[gg][o];
        float h = fmaxf(s1, 0.f);

        float s2 = b2[o];
#pragma unroll
        for (int k = 0; k < 32; k++)
            s2 = fmaf(__shfl_sync(0xffffffffu, h, k), w2[k * 32 + o], s2);
        h = fmaxf(s2, 0.f);

        float s3 = b3[o];
#pragma unroll
        for (int k = 0; k < 32; k++)
            s3 = fmaf(__shfl_sync(0xffffffffu, h, k), w3[k * 32 + o], s3);
        h = fmaxf(s3, 0.f);

        float v = h * w4[o];
#pragma unroll
        for (int off = 16; off; off >>= 1) v += __shfl_xor_sync(0xffffffffu, v, off);
        if (o == 0) out[b] = v + b4[0];
    }
}

// ---------------------------------------------------------------------------
extern "C" void kernel_launch(void* const* d_in, const int* in_sizes, int n_in,
                              void* d_out, int out_size)
{
    const float* x  = (const float*)d_in[0];
    const float* cw = (const float*)d_in[1];
    const float* cb = (const float*)d_in[2];
    const float* w1 = (const float*)d_in[3];
    const float* b1 = (const float*)d_in[4];
    const float* w2 = (const float*)d_in[5];
    const float* b2 = (const float*)d_in[6];
    const float* w3 = (const float*)d_in[7];
    const float* b3 = (const float*)d_in[8];
    const float* w4 = (const float*)d_in[9];
    const float* b4 = (const float*)d_in[10];
    float* out = (float*)d_out;

    fused_conv_sig_kernel<<<dim3(4, B_), 400>>>(x, cw, cb);
    mlp1_kernel<<<NCHUNK_, 256>>>(w1);
    mlp_tail_kernel<<<B_, 256>>>(b1, w2, b2, w3, b3, w4, b4, out);
}